// round 9
// baseline (speedup 1.0000x reference)
#include <cuda_runtime.h>
#include <cuda_fp16.h>
#include <math.h>
#include <stdint.h>

#define B_ROWS 8192
#define D_IN   784
#define D_H    4096
#define D_OUT  10
#define THRESH 0.1f

#define KPAD   832          // 784 padded to 26*32
#define KITER  26           // K chunks of 32 halves
#define NST    4            // cp.async pipeline stages

// ---------------- device scratch ----------------
__device__ __half g_xhi[(size_t)B_ROWS * KPAD];
__device__ __half g_xlo[(size_t)B_ROWS * KPAD];
__device__ __half g_w1h[(size_t)D_H * KPAD];
__device__ float  g_h[(size_t)B_ROWS * D_H];
__device__ int    g_w2q[D_OUT * (D_H / 4)];     // packed int8 ternary w2
__device__ unsigned int g_maxbits;

// ---------------- helpers ----------------
__device__ __forceinline__ uint32_t smem_to_u32(const void* p) {
    uint32_t a;
    asm("{ .reg .u64 t; cvta.to.shared.u64 t, %1; cvt.u32.u64 %0, t; }" : "=r"(a) : "l"(p));
    return a;
}
__device__ __forceinline__ void cp16(uint32_t s, const void* g) {
    asm volatile("cp.async.cg.shared.global [%0], [%1], 16;" :: "r"(s), "l"(g));
}
__device__ __forceinline__ void ldsm_x4(uint32_t* r, uint32_t addr) {
    asm volatile("ldmatrix.sync.aligned.m8n8.x4.shared.b16 {%0,%1,%2,%3}, [%4];"
        : "=r"(r[0]), "=r"(r[1]), "=r"(r[2]), "=r"(r[3]) : "r"(addr));
}
__device__ __forceinline__ void mma16816(float* c, const uint32_t* a, const uint32_t* b) {
    asm volatile(
        "mma.sync.aligned.m16n8k16.row.col.f32.f16.f16.f32 "
        "{%0,%1,%2,%3}, {%4,%5,%6,%7}, {%8,%9}, {%0,%1,%2,%3};"
        : "+f"(c[0]), "+f"(c[1]), "+f"(c[2]), "+f"(c[3])
        : "r"(a[0]), "r"(a[1]), "r"(a[2]), "r"(a[3]), "r"(b[0]), "r"(b[1]));
}
__device__ __forceinline__ int dp4a_s(int a, int b, int c) {
    int d;
    asm("dp4a.s32.s32 %0, %1, %2, %3;" : "=r"(d) : "r"(a), "r"(b), "r"(c));
    return d;
}

__device__ __forceinline__ float ternf(float v) {
    return (v > THRESH) ? 1.0f : ((v < -THRESH) ? -1.0f : 0.0f);
}
__device__ __forceinline__ int terni(float v) {
    return (v > THRESH) ? 1 : ((v < -THRESH) ? -1 : 0);
}

// ---------------- prep kernels ----------------
__global__ void prep_x_kernel(const float* __restrict__ x) {
    int g = blockIdx.x * 256 + threadIdx.x;        // group of 8 elements
    if (g == 0) g_maxbits = 0u;
    int row = g / 104, part = g - row * 104;       // 104 groups of 8 = 832
    __align__(16) __half hh[8];
    __align__(16) __half ll[8];
    if (part < 98) {
        const float4* p = (const float4*)(x + (size_t)row * D_IN + part * 8);
        float4 a = p[0], b = p[1];
        float v[8] = {a.x, a.y, a.z, a.w, b.x, b.y, b.z, b.w};
#pragma unroll
        for (int i = 0; i < 8; i++) {
            __half h = __float2half_rn(v[i]);
            float r = v[i] - __half2float(h);
            hh[i] = h;
            ll[i] = __float2half_rn(r);
        }
    } else {
#pragma unroll
        for (int i = 0; i < 8; i++) { hh[i] = __ushort_as_half(0); ll[i] = __ushort_as_half(0); }
    }
    *(uint4*)(g_xhi + (size_t)g * 8) = *(uint4*)hh;
    *(uint4*)(g_xlo + (size_t)g * 8) = *(uint4*)ll;
}

// blocks [0, 1664): ternarize w1 -> fp16. block 1664: pack ternary w2 -> int8x4.
__global__ void prep_w_kernel(const float* __restrict__ w1, const float* __restrict__ w2) {
    if (blockIdx.x < (D_H * 104) / 256) {
        int g = blockIdx.x * 256 + threadIdx.x;
        int row = g / 104, part = g - row * 104;
        __align__(16) __half hh[8];
        if (part < 98) {
            const float4* p = (const float4*)(w1 + (size_t)row * D_IN + part * 8);
            float4 a = p[0], b = p[1];
            float v[8] = {a.x, a.y, a.z, a.w, b.x, b.y, b.z, b.w};
#pragma unroll
            for (int i = 0; i < 8; i++) hh[i] = __float2half_rn(ternf(v[i]));
        } else {
#pragma unroll
            for (int i = 0; i < 8; i++) hh[i] = __ushort_as_half(0);
        }
        *(uint4*)(g_w1h + (size_t)g * 8) = *(uint4*)hh;
    } else {
        // pack w2: 10*1024 words, 256 threads -> 40 iters
        for (int i = threadIdx.x; i < D_OUT * (D_H / 4); i += 256) {
            const float4 v = *(const float4*)(w2 + (size_t)i * 4);
            uint32_t p = (uint32_t)(terni(v.x) & 0xff)
                       | ((uint32_t)(terni(v.y) & 0xff) << 8)
                       | ((uint32_t)(terni(v.z) & 0xff) << 16)
                       | ((uint32_t)(terni(v.w) & 0xff) << 24);
            g_w2q[i] = (int)p;
        }
    }
}

// ---------------- gemm1: HMMA, CTA M128 x N256, warp 64x64, hi/lo fp16 split ----------------
// Per-stage smem: A_hi 8KB | A_lo 8KB | B 16KB = 32KB; 4 stages = 128KB; bias 1KB.
#define STAGE    32768
#define OFF_ALO  8192
#define OFF_B    16384
#define OFF_BIAS (STAGE * NST)          // 131072
#define SMEM_REQ (OFF_BIAS + 1024)

__global__ void __launch_bounds__(256, 1) gemm1_mma_kernel(const float* __restrict__ b1) {
    extern __shared__ char smem_raw[];
    const uint32_t sb = smem_to_u32(smem_raw);
    float* s_bias = (float*)(smem_raw + OFF_BIAS);

    const int tid    = threadIdx.x;
    const int lane   = tid & 31;
    const int wid    = tid >> 5;
    const int warp_m = wid >> 2;         // 2 warps over M (64 rows each)
    const int warp_n = wid & 3;          // 4 warps over N (64 cols each)
    const int bm = blockIdx.y * 128;
    const int bn = blockIdx.x * 256;

    s_bias[tid] = b1[bn + tid];

    // ---- cp.async precompute: A 2 chunks/thread (hi & lo each), B 4 chunks/thread ----
    size_t   a_goff[2];
    uint32_t a_sw[2];
#pragma unroll
    for (int j = 0; j < 2; j++) {
        int idx = tid + j * 256;          // 0..511
        int row = idx >> 2;               // 0..127
        int ch  = idx & 3;
        a_sw[j]   = (uint32_t)(row * 64 + ((ch ^ ((row >> 1) & 3)) << 4));
        a_goff[j] = (size_t)(bm + row) * KPAD + ch * 8;
    }
    size_t   b_goff[4];
    uint32_t b_sw[4];
#pragma unroll
    for (int j = 0; j < 4; j++) {
        int idx = tid + j * 256;          // 0..1023
        int row = idx >> 2;               // 0..255
        int ch  = idx & 3;
        b_sw[j]   = (uint32_t)(row * 64 + ((ch ^ ((row >> 1) & 3)) << 4));
        b_goff[j] = (size_t)(bn + row) * KPAD + ch * 8;
    }

    // ---- ldmatrix address precompute ----
    const int a_row = warp_m * 64 + (lane & 15);
    const int a_sel = (a_row >> 1) & 3;
    uint32_t a_base[2];
#pragma unroll
    for (int kk = 0; kk < 2; kk++)
        a_base[kk] = (uint32_t)(a_row * 64 + (((kk * 2 + (lane >> 4)) ^ a_sel) << 4));
    const int n_off = ((lane >> 4) & 1) * 8 + (lane & 7);
    const int cpar  = (lane >> 3) & 1;
    const int b_row = warp_n * 64 + n_off;
    const int b_sel = (b_row >> 1) & 3;
    uint32_t b_base[2];
#pragma unroll
    for (int kk = 0; kk < 2; kk++)
        b_base[kk] = (uint32_t)(b_row * 64 + (((kk * 2 + cpar) ^ b_sel) << 4));

    float acc[4][8][4];
#pragma unroll
    for (int mt = 0; mt < 4; mt++)
#pragma unroll
        for (int nt = 0; nt < 8; nt++)
#pragma unroll
            for (int r = 0; r < 4; r++) acc[mt][nt][r] = 0.0f;

    // ---- prologue ----
#pragma unroll
    for (int s = 0; s < NST - 1; s++) {
        const uint32_t st = sb + s * STAGE;
        const int k0 = s * 32;
#pragma unroll
        for (int j = 0; j < 2; j++) {
            cp16(st + a_sw[j],           g_xhi + a_goff[j] + k0);
            cp16(st + OFF_ALO + a_sw[j], g_xlo + a_goff[j] + k0);
        }
#pragma unroll
        for (int j = 0; j < 4; j++)
            cp16(st + OFF_B + b_sw[j],   g_w1h + b_goff[j] + k0);
        asm volatile("cp.async.commit_group;");
    }

    // ---- mainloop ----
    int fetch = NST - 1;
#pragma unroll 1
    for (int c = 0; c < KITER; c++) {
        asm volatile("cp.async.wait_group 2;");
        __syncthreads();

        if (fetch < KITER) {
            const uint32_t st = sb + (fetch & 3) * STAGE;
            const int k0 = fetch * 32;
#pragma unroll
            for (int j = 0; j < 2; j++) {
                cp16(st + a_sw[j],           g_xhi + a_goff[j] + k0);
                cp16(st + OFF_ALO + a_sw[j], g_xlo + a_goff[j] + k0);
            }
#pragma unroll
            for (int j = 0; j < 4; j++)
                cp16(st + OFF_B + b_sw[j],   g_w1h + b_goff[j] + k0);
        }
        asm volatile("cp.async.commit_group;");
        fetch++;

        const uint32_t st = sb + (c & 3) * STAGE;
#pragma unroll
        for (int kk = 0; kk < 2; kk++) {
            uint32_t ah[4][4], al[4][4], bfr[4][4];
#pragma unroll
            for (int mt = 0; mt < 4; mt++) {
                ldsm_x4(ah[mt], st + a_base[kk] + mt * 1024);
                ldsm_x4(al[mt], st + OFF_ALO + a_base[kk] + mt * 1024);
            }
#pragma unroll
            for (int nt2 = 0; nt2 < 4; nt2++)
                ldsm_x4(bfr[nt2], st + OFF_B + b_base[kk] + nt2 * 1024);
#pragma unroll
            for (int mt = 0; mt < 4; mt++)
#pragma unroll
                for (int nt = 0; nt < 8; nt++) {
                    const uint32_t* bp2 = &bfr[nt >> 1][(nt & 1) * 2];
                    mma16816(acc[mt][nt], ah[mt], bp2);
                    mma16816(acc[mt][nt], al[mt], bp2);
                }
        }
    }

    // ---- epilogue: bias + relu + store + max ----
    __shared__ float wmax[8];
    const int qrow  = lane >> 2;
    const int qcol2 = (lane & 3) * 2;
    float lmax = 0.0f;
#pragma unroll
    for (int mt = 0; mt < 4; mt++) {
#pragma unroll
        for (int nt = 0; nt < 8; nt++) {
            const int nl = warp_n * 64 + nt * 8 + qcol2;
            const int m0 = bm + warp_m * 64 + mt * 16 + qrow;
            const float bb0 = s_bias[nl], bb1 = s_bias[nl + 1];
            float v0 = fmaxf(acc[mt][nt][0] + bb0, 0.0f);
            float v1 = fmaxf(acc[mt][nt][1] + bb1, 0.0f);
            float v2 = fmaxf(acc[mt][nt][2] + bb0, 0.0f);
            float v3 = fmaxf(acc[mt][nt][3] + bb1, 0.0f);
            lmax = fmaxf(fmaxf(lmax, fmaxf(v0, v1)), fmaxf(v2, v3));
            float2 p0 = make_float2(v0, v1);
            float2 p1 = make_float2(v2, v3);
            *(float2*)(g_h + (size_t)m0 * D_H + bn + nl)       = p0;
            *(float2*)(g_h + (size_t)(m0 + 8) * D_H + bn + nl) = p1;
        }
    }
#pragma unroll
    for (int off = 16; off > 0; off >>= 1)
        lmax = fmaxf(lmax, __shfl_xor_sync(0xffffffffu, lmax, off));
    if (lane == 0) wmax[wid] = lmax;
    __syncthreads();
    if (tid == 0) {
        float m = wmax[0];
#pragma unroll
        for (int i = 1; i < 8; i++) m = fmaxf(m, wmax[i]);
        atomicMax(&g_maxbits, __float_as_uint(m));
    }
}

// ---------------- kernel 2: quant(int8) + dp4a layer2 + log_softmax ----------------
__global__ __launch_bounds__(256) void layer2_kernel(
    const float* __restrict__ b2,
    float* __restrict__ out)
{
    __shared__ int ws[D_OUT * (D_H / 4)];  // 40 KB packed int8 ternary w2

    const int tid = threadIdx.x;
#pragma unroll
    for (int i = 0; i < (D_OUT * (D_H / 4)) / 256; i++)
        ws[tid + i * 256] = g_w2q[tid + i * 256];
    __syncthreads();

    const float maxv  = __uint_as_float(g_maxbits);
    const float scale = 127.0f / maxv;

    const int lane = tid & 31, warp = tid >> 5;
    const int row  = blockIdx.x * 8 + warp;

    const float4* hrow = (const float4*)(g_h + (size_t)row * D_H);

    int acc[D_OUT];
#pragma unroll
    for (int c = 0; c < D_OUT; c++) acc[c] = 0;

#pragma unroll 4
    for (int it = lane; it < D_H / 4; it += 32) {
        float4 h4 = hrow[it];
        int q0 = __float2int_rn(fminf(h4.x * scale, 127.0f));
        int q1 = __float2int_rn(fminf(h4.y * scale, 127.0f));
        int q2 = __float2int_rn(fminf(h4.z * scale, 127.0f));
        int q3 = __float2int_rn(fminf(h4.w * scale, 127.0f));
        int pk = (int)((uint32_t)q0 | ((uint32_t)q1 << 8) | ((uint32_t)q2 << 16) | ((uint32_t)q3 << 24));
#pragma unroll
        for (int c = 0; c < D_OUT; c++)
            acc[c] = dp4a_s(pk, ws[c * (D_H / 4) + it], acc[c]);
    }

#pragma unroll
    for (int off = 16; off > 0; off >>= 1)
#pragma unroll
        for (int c = 0; c < D_OUT; c++)
            acc[c] += __shfl_xor_sync(0xffffffffu, acc[c], off);

    if (lane == 0) {
        float l[D_OUT];
        float m = -1e30f;
#pragma unroll
        for (int c = 0; c < D_OUT; c++) {
            l[c] = (float)acc[c] / scale + b2[c];
            m = fmaxf(m, l[c]);
        }
        float s = 0.0f;
#pragma unroll
        for (int c = 0; c < D_OUT; c++) s += expf(l[c] - m);
        float lse = m + logf(s);
        float* orow = out + (size_t)row * D_OUT;
#pragma unroll
        for (int c = 0; c < D_OUT; c++) orow[c] = l[c] - lse;
    }
}

// ---------------- launch ----------------
extern "C" void kernel_launch(void* const* d_in, const int* in_sizes, int n_in,
                              void* d_out, int out_size)
{
    const float* x  = (const float*)d_in[0];
    const float* w1 = (const float*)d_in[1];
    const float* b1 = (const float*)d_in[2];
    const float* w2 = (const float*)d_in[3];
    const float* b2 = (const float*)d_in[4];
    float* out = (float*)d_out;

    cudaFuncSetAttribute(gemm1_mma_kernel, cudaFuncAttributeMaxDynamicSharedMemorySize, SMEM_REQ);

    prep_x_kernel<<<(B_ROWS * 104) / 256, 256>>>(x);         // also resets g_maxbits
    prep_w_kernel<<<(D_H * 104) / 256 + 1, 256>>>(w1, w2);   // w1 ternarize + w2 pack

    dim3 g1(D_H / 256, B_ROWS / 128);  // (16, 64)
    gemm1_mma_kernel<<<g1, 256, SMEM_REQ>>>(b1);

    layer2_kernel<<<B_ROWS / 8, 256>>>(b2, out);
}

// round 11
// speedup vs baseline: 1.1576x; 1.1576x over previous
#include <cuda_runtime.h>
#include <cuda_fp16.h>
#include <math.h>
#include <stdint.h>

#define B_ROWS 8192
#define D_IN   784
#define D_H    4096
#define D_OUT  10
#define THRESH 0.1f

#define KPAD   800          // 784 padded to 25*32
#define GPR    100          // 16B-groups per row (KPAD/8)
#define KITER  25           // K chunks of 32 halves
#define NST    4            // cp.async pipeline stages

// ---------------- device scratch ----------------
__device__ __half g_xhi[(size_t)B_ROWS * KPAD];
__device__ __half g_xlo[(size_t)B_ROWS * KPAD];
__device__ __half g_w1h[(size_t)D_H * KPAD];
__device__ float  g_h[(size_t)B_ROWS * D_H];
__device__ int    g_w2q[D_OUT * (D_H / 4)];     // packed int8 ternary w2
__device__ unsigned int g_maxbits;

// ---------------- helpers ----------------
__device__ __forceinline__ uint32_t smem_to_u32(const void* p) {
    uint32_t a;
    asm("{ .reg .u64 t; cvta.to.shared.u64 t, %1; cvt.u32.u64 %0, t; }" : "=r"(a) : "l"(p));
    return a;
}
__device__ __forceinline__ void cp16(uint32_t s, const void* g) {
    asm volatile("cp.async.cg.shared.global [%0], [%1], 16;" :: "r"(s), "l"(g));
}
__device__ __forceinline__ void ldsm_x4(uint32_t* r, uint32_t addr) {
    asm volatile("ldmatrix.sync.aligned.m8n8.x4.shared.b16 {%0,%1,%2,%3}, [%4];"
        : "=r"(r[0]), "=r"(r[1]), "=r"(r[2]), "=r"(r[3]) : "r"(addr));
}
__device__ __forceinline__ void mma16816(float* c, const uint32_t* a, const uint32_t* b) {
    asm volatile(
        "mma.sync.aligned.m16n8k16.row.col.f32.f16.f16.f32 "
        "{%0,%1,%2,%3}, {%4,%5,%6,%7}, {%8,%9}, {%0,%1,%2,%3};"
        : "+f"(c[0]), "+f"(c[1]), "+f"(c[2]), "+f"(c[3])
        : "r"(a[0]), "r"(a[1]), "r"(a[2]), "r"(a[3]), "r"(b[0]), "r"(b[1]));
}
__device__ __forceinline__ int dp4a_s(int a, int b, int c) {
    int d;
    asm("dp4a.s32.s32 %0, %1, %2, %3;" : "=r"(d) : "r"(a), "r"(b), "r"(c));
    return d;
}

__device__ __forceinline__ float ternf(float v) {
    return (v > THRESH) ? 1.0f : ((v < -THRESH) ? -1.0f : 0.0f);
}
__device__ __forceinline__ int terni(float v) {
    return (v > THRESH) ? 1 : ((v < -THRESH) ? -1 : 0);
}

// ---------------- fused prep kernel ----------------
// blocks [0, XB): x -> hi/lo fp16.  [XB, XB+WB): w1 ternarize -> fp16.  [XB+WB]: pack w2.
#define XB ((B_ROWS * GPR) / 256)   // 3200
#define WB ((D_H * GPR) / 256)      // 1600

__global__ void prep_kernel(const float* __restrict__ x,
                            const float* __restrict__ w1,
                            const float* __restrict__ w2) {
    const int b = blockIdx.x;
    if (b < XB) {
        int g = b * 256 + threadIdx.x;             // group of 8 elements
        if (g == 0) g_maxbits = 0u;
        int row = g / GPR, part = g - row * GPR;
        __align__(16) __half hh[8];
        __align__(16) __half ll[8];
        if (part < 98) {
            const float4* p = (const float4*)(x + (size_t)row * D_IN + part * 8);
            float4 a = p[0], bb = p[1];
            float v[8] = {a.x, a.y, a.z, a.w, bb.x, bb.y, bb.z, bb.w};
#pragma unroll
            for (int i = 0; i < 8; i++) {
                __half h = __float2half_rn(v[i]);
                float r = v[i] - __half2float(h);
                hh[i] = h;
                ll[i] = __float2half_rn(r);
            }
        } else {
#pragma unroll
            for (int i = 0; i < 8; i++) { hh[i] = __ushort_as_half(0); ll[i] = __ushort_as_half(0); }
        }
        *(uint4*)(g_xhi + (size_t)g * 8) = *(uint4*)hh;
        *(uint4*)(g_xlo + (size_t)g * 8) = *(uint4*)ll;
    } else if (b < XB + WB) {
        int g = (b - XB) * 256 + threadIdx.x;
        int row = g / GPR, part = g - row * GPR;
        __align__(16) __half hh[8];
        if (part < 98) {
            const float4* p = (const float4*)(w1 + (size_t)row * D_IN + part * 8);
            float4 a = p[0], bb = p[1];
            float v[8] = {a.x, a.y, a.z, a.w, bb.x, bb.y, bb.z, bb.w};
#pragma unroll
            for (int i = 0; i < 8; i++) hh[i] = __float2half_rn(ternf(v[i]));
        } else {
#pragma unroll
            for (int i = 0; i < 8; i++) hh[i] = __ushort_as_half(0);
        }
        *(uint4*)(g_w1h + (size_t)g * 8) = *(uint4*)hh;
    } else {
        // pack w2: 10*1024 words, 256 threads -> 40 iters
        for (int i = threadIdx.x; i < D_OUT * (D_H / 4); i += 256) {
            const float4 v = *(const float4*)(w2 + (size_t)i * 4);
            uint32_t p = (uint32_t)(terni(v.x) & 0xff)
                       | ((uint32_t)(terni(v.y) & 0xff) << 8)
                       | ((uint32_t)(terni(v.z) & 0xff) << 16)
                       | ((uint32_t)(terni(v.w) & 0xff) << 24);
            g_w2q[i] = (int)p;
        }
    }
}

// ---------------- gemm1: legacy HMMA (mma.sync) M128 x N128, hi/lo fp16 split ----------------
// Per-stage smem: A_hi 8KB | A_lo 8KB | B 8KB = 24KB; 4 stages = 96KB; bias 512B.
#define STAGE    24576
#define OFF_ALO  8192
#define OFF_B    16384
#define OFF_BIAS (STAGE * NST)          // 98304
#define SMEM_REQ (OFF_BIAS + 512)

__global__ void __launch_bounds__(256, 2) gemm1_mma_kernel(const float* __restrict__ b1) {
    extern __shared__ char smem_raw[];
    const uint32_t sb = smem_to_u32(smem_raw);
    float* s_bias = (float*)(smem_raw + OFF_BIAS);

    const int tid    = threadIdx.x;
    const int lane   = tid & 31;
    const int wid    = tid >> 5;
    const int warp_m = wid & 3;          // 4 warps over M (32 rows each)
    const int warp_n = wid >> 2;         // 2 warps over N (64 cols each)
    const int bm = blockIdx.y * 128;
    const int bn = blockIdx.x * 128;

    if (tid < 128) s_bias[tid] = b1[bn + tid];

    // ---- per-thread cp.async source/dest precompute (2 x 16B per array per stage) ----
    size_t   a_goff[2], b_goff[2];
    uint32_t sw_off[2];
#pragma unroll
    for (int j = 0; j < 2; j++) {
        int idx = tid + j * 256;          // 0..511
        int row = idx >> 2;               // 0..127
        int ch  = idx & 3;                // 16B chunk within 64B row
        sw_off[j] = (uint32_t)(row * 64 + ((ch ^ ((row >> 1) & 3)) << 4));
        a_goff[j] = (size_t)(bm + row) * KPAD + ch * 8;
        b_goff[j] = (size_t)(bn + row) * KPAD + ch * 8;
    }

    // ---- ldmatrix address precompute ----
    const int a_row = warp_m * 32 + (lane & 15);
    const int a_sel = (a_row >> 1) & 3;
    uint32_t a_base[2];
#pragma unroll
    for (int kk = 0; kk < 2; kk++)
        a_base[kk] = (uint32_t)(a_row * 64 + (((kk * 2 + (lane >> 4)) ^ a_sel) << 4));
    const int n_off = ((lane >> 4) & 1) * 8 + (lane & 7);
    const int cpar  = (lane >> 3) & 1;
    const int b_row = warp_n * 64 + n_off;
    const int b_sel = (b_row >> 1) & 3;
    uint32_t b_base[2];
#pragma unroll
    for (int kk = 0; kk < 2; kk++)
        b_base[kk] = (uint32_t)(b_row * 64 + (((kk * 2 + cpar) ^ b_sel) << 4));

    float acc[2][8][4];
#pragma unroll
    for (int mt = 0; mt < 2; mt++)
#pragma unroll
        for (int nt = 0; nt < 8; nt++)
#pragma unroll
            for (int r = 0; r < 4; r++) acc[mt][nt][r] = 0.0f;

    // ---- prologue ----
#pragma unroll
    for (int s = 0; s < NST - 1; s++) {
        const uint32_t st = sb + s * STAGE;
        const int k0 = s * 32;
#pragma unroll
        for (int j = 0; j < 2; j++) {
            cp16(st + sw_off[j],           g_xhi + a_goff[j] + k0);
            cp16(st + OFF_ALO + sw_off[j], g_xlo + a_goff[j] + k0);
            cp16(st + OFF_B + sw_off[j],   g_w1h + b_goff[j] + k0);
        }
        asm volatile("cp.async.commit_group;");
    }

    // ---- mainloop ----
    int fetch = NST - 1;
#pragma unroll 1
    for (int c = 0; c < KITER; c++) {
        asm volatile("cp.async.wait_group 2;");
        __syncthreads();

        if (fetch < KITER) {
            const uint32_t st = sb + (fetch & 3) * STAGE;
            const int k0 = fetch * 32;
#pragma unroll
            for (int j = 0; j < 2; j++) {
                cp16(st + sw_off[j],           g_xhi + a_goff[j] + k0);
                cp16(st + OFF_ALO + sw_off[j], g_xlo + a_goff[j] + k0);
                cp16(st + OFF_B + sw_off[j],   g_w1h + b_goff[j] + k0);
            }
        }
        asm volatile("cp.async.commit_group;");
        fetch++;

        const uint32_t st = sb + (c & 3) * STAGE;
#pragma unroll
        for (int kk = 0; kk < 2; kk++) {
            uint32_t ah[2][4], al[2][4], bfr[4][4];
#pragma unroll
            for (int mt = 0; mt < 2; mt++) {
                ldsm_x4(ah[mt], st + a_base[kk] + mt * 1024);
                ldsm_x4(al[mt], st + OFF_ALO + a_base[kk] + mt * 1024);
            }
#pragma unroll
            for (int nt2 = 0; nt2 < 4; nt2++)
                ldsm_x4(bfr[nt2], st + OFF_B + b_base[kk] + nt2 * 1024);
#pragma unroll
            for (int mt = 0; mt < 2; mt++)
#pragma unroll
                for (int nt = 0; nt < 8; nt++) {
                    const uint32_t* bp2 = &bfr[nt >> 1][(nt & 1) * 2];
                    mma16816(acc[mt][nt], ah[mt], bp2);
                    mma16816(acc[mt][nt], al[mt], bp2);
                }
        }
    }

    // ---- epilogue: bias + relu + store + max ----
    __shared__ float wmax[8];
    const int qrow  = lane >> 2;
    const int qcol2 = (lane & 3) * 2;
    float lmax = 0.0f;
#pragma unroll
    for (int mt = 0; mt < 2; mt++) {
#pragma unroll
        for (int nt = 0; nt < 8; nt++) {
            const int nl = warp_n * 64 + nt * 8 + qcol2;
            const int m0 = bm + warp_m * 32 + mt * 16 + qrow;
            const float bb0 = s_bias[nl], bb1 = s_bias[nl + 1];
            float v0 = fmaxf(acc[mt][nt][0] + bb0, 0.0f);
            float v1 = fmaxf(acc[mt][nt][1] + bb1, 0.0f);
            float v2 = fmaxf(acc[mt][nt][2] + bb0, 0.0f);
            float v3 = fmaxf(acc[mt][nt][3] + bb1, 0.0f);
            lmax = fmaxf(fmaxf(lmax, fmaxf(v0, v1)), fmaxf(v2, v3));
            float2 p0 = make_float2(v0, v1);
            float2 p1 = make_float2(v2, v3);
            *(float2*)(g_h + (size_t)m0 * D_H + bn + nl)       = p0;
            *(float2*)(g_h + (size_t)(m0 + 8) * D_H + bn + nl) = p1;
        }
    }
#pragma unroll
    for (int off = 16; off > 0; off >>= 1)
        lmax = fmaxf(lmax, __shfl_xor_sync(0xffffffffu, lmax, off));
    if (lane == 0) wmax[wid] = lmax;
    __syncthreads();
    if (tid == 0) {
        float m = wmax[0];
#pragma unroll
        for (int i = 1; i < 8; i++) m = fmaxf(m, wmax[i]);
        atomicMax(&g_maxbits, __float_as_uint(m));
    }
}

// ---------------- kernel 2: quant(int8) + dp4a layer2 + log_softmax ----------------
__global__ __launch_bounds__(256) void layer2_kernel(
    const float* __restrict__ b2,
    float* __restrict__ out)
{
    __shared__ int ws[D_OUT * (D_H / 4)];  // 40 KB packed int8 ternary w2

    const int tid = threadIdx.x;
#pragma unroll
    for (int i = 0; i < (D_OUT * (D_H / 4)) / 256; i++)
        ws[tid + i * 256] = g_w2q[tid + i * 256];
    __syncthreads();

    const float maxv  = __uint_as_float(g_maxbits);
    const float scale = 127.0f / maxv;

    const int lane = tid & 31, warp = tid >> 5;
    const int row  = blockIdx.x * 8 + warp;

    const float4* hrow = (const float4*)(g_h + (size_t)row * D_H);

    int acc[D_OUT];
#pragma unroll
    for (int c = 0; c < D_OUT; c++) acc[c] = 0;

#pragma unroll 4
    for (int it = lane; it < D_H / 4; it += 32) {
        float4 h4 = hrow[it];
        int q0 = __float2int_rn(fminf(h4.x * scale, 127.0f));
        int q1 = __float2int_rn(fminf(h4.y * scale, 127.0f));
        int q2 = __float2int_rn(fminf(h4.z * scale, 127.0f));
        int q3 = __float2int_rn(fminf(h4.w * scale, 127.0f));
        int pk = (int)((uint32_t)q0 | ((uint32_t)q1 << 8) | ((uint32_t)q2 << 16) | ((uint32_t)q3 << 24));
#pragma unroll
        for (int c = 0; c < D_OUT; c++)
            acc[c] = dp4a_s(pk, ws[c * (D_H / 4) + it], acc[c]);
    }

#pragma unroll
    for (int off = 16; off > 0; off >>= 1)
#pragma unroll
        for (int c = 0; c < D_OUT; c++)
            acc[c] += __shfl_xor_sync(0xffffffffu, acc[c], off);

    if (lane == 0) {
        float l[D_OUT];
        float m = -1e30f;
#pragma unroll
        for (int c = 0; c < D_OUT; c++) {
            l[c] = (float)acc[c] / scale + b2[c];
            m = fmaxf(m, l[c]);
        }
        float s = 0.0f;
#pragma unroll
        for (int c = 0; c < D_OUT; c++) s += expf(l[c] - m);
        float lse = m + logf(s);
        float* orow = out + (size_t)row * D_OUT;
#pragma unroll
        for (int c = 0; c < D_OUT; c++) orow[c] = l[c] - lse;
    }
}

// ---------------- launch ----------------
extern "C" void kernel_launch(void* const* d_in, const int* in_sizes, int n_in,
                              void* d_out, int out_size)
{
    const float* x  = (const float*)d_in[0];
    const float* w1 = (const float*)d_in[1];
    const float* b1 = (const float*)d_in[2];
    const float* w2 = (const float*)d_in[3];
    const float* b2 = (const float*)d_in[4];
    float* out = (float*)d_out;

    cudaFuncSetAttribute(gemm1_mma_kernel, cudaFuncAttributeMaxDynamicSharedMemorySize, SMEM_REQ);

    prep_kernel<<<XB + WB + 1, 256>>>(x, w1, w2);   // x split + w1 ternarize + w2 pack + max reset

    dim3 g1(D_H / 128, B_ROWS / 128);  // (32, 64)
    gemm1_mma_kernel<<<g1, 256, SMEM_REQ>>>(b1);

    layer2_kernel<<<B_ROWS / 8, 256>>>(b2, out);
}

// round 12
// speedup vs baseline: 1.1582x; 1.0005x over previous
#include <cuda_runtime.h>
#include <cuda_fp16.h>
#include <math.h>
#include <stdint.h>

#define B_ROWS 8192
#define D_IN   784
#define D_H    4096
#define D_OUT  10
#define THRESH 0.1f

#define KPAD   800          // 784 padded to 25*32
#define GPR    100          // 16B-groups per row (KPAD/8)
#define KITER  25           // K chunks of 32 halves
#define NST    4            // cp.async pipeline stages

// ---------------- device scratch ----------------
__device__ __half g_xhi[(size_t)B_ROWS * KPAD];
__device__ __half g_xlo[(size_t)B_ROWS * KPAD];
__device__ __half g_w1h[(size_t)D_H * KPAD];
__device__ float  g_h[(size_t)B_ROWS * D_H];
__device__ int    g_w2q[D_OUT * (D_H / 4)];     // packed int8 ternary w2
__device__ unsigned int g_maxbits;

// ---------------- helpers ----------------
__device__ __forceinline__ uint32_t smem_to_u32(const void* p) {
    uint32_t a;
    asm("{ .reg .u64 t; cvta.to.shared.u64 t, %1; cvt.u32.u64 %0, t; }" : "=r"(a) : "l"(p));
    return a;
}
__device__ __forceinline__ void cp16(uint32_t s, const void* g) {
    asm volatile("cp.async.cg.shared.global [%0], [%1], 16;" :: "r"(s), "l"(g));
}
__device__ __forceinline__ void ldsm_x4(uint32_t* r, uint32_t addr) {
    asm volatile("ldmatrix.sync.aligned.m8n8.x4.shared.b16 {%0,%1,%2,%3}, [%4];"
        : "=r"(r[0]), "=r"(r[1]), "=r"(r[2]), "=r"(r[3]) : "r"(addr));
}
__device__ __forceinline__ void mma16816(float* c, const uint32_t* a, const uint32_t* b) {
    asm volatile(
        "mma.sync.aligned.m16n8k16.row.col.f32.f16.f16.f32 "
        "{%0,%1,%2,%3}, {%4,%5,%6,%7}, {%8,%9}, {%0,%1,%2,%3};"
        : "+f"(c[0]), "+f"(c[1]), "+f"(c[2]), "+f"(c[3])
        : "r"(a[0]), "r"(a[1]), "r"(a[2]), "r"(a[3]), "r"(b[0]), "r"(b[1]));
}
__device__ __forceinline__ int dp4a_s(int a, int b, int c) {
    int d;
    asm("dp4a.s32.s32 %0, %1, %2, %3;" : "=r"(d) : "r"(a), "r"(b), "r"(c));
    return d;
}

__device__ __forceinline__ float ternf(float v) {
    return (v > THRESH) ? 1.0f : ((v < -THRESH) ? -1.0f : 0.0f);
}
__device__ __forceinline__ int terni(float v) {
    return (v > THRESH) ? 1 : ((v < -THRESH) ? -1 : 0);
}

// ---------------- fused prep kernel ----------------
// blocks [0, XB): x -> hi/lo fp16.  [XB, XB+WB): w1 ternarize -> fp16.  [XB+WB]: pack w2.
#define XB ((B_ROWS * GPR) / 256)   // 3200
#define WB ((D_H * GPR) / 256)      // 1600

__global__ void prep_kernel(const float* __restrict__ x,
                            const float* __restrict__ w1,
                            const float* __restrict__ w2) {
    const int b = blockIdx.x;
    if (b < XB) {
        int g = b * 256 + threadIdx.x;             // group of 8 elements
        if (g == 0) g_maxbits = 0u;
        int row = g / GPR, part = g - row * GPR;
        __align__(16) __half hh[8];
        __align__(16) __half ll[8];
        if (part < 98) {
            const float4* p = (const float4*)(x + (size_t)row * D_IN + part * 8);
            float4 a = p[0], bb = p[1];
            float v[8] = {a.x, a.y, a.z, a.w, bb.x, bb.y, bb.z, bb.w};
#pragma unroll
            for (int i = 0; i < 8; i++) {
                __half h = __float2half_rn(v[i]);
                float r = v[i] - __half2float(h);
                hh[i] = h;
                ll[i] = __float2half_rn(r);
            }
        } else {
#pragma unroll
            for (int i = 0; i < 8; i++) { hh[i] = __ushort_as_half(0); ll[i] = __ushort_as_half(0); }
        }
        *(uint4*)(g_xhi + (size_t)g * 8) = *(uint4*)hh;
        *(uint4*)(g_xlo + (size_t)g * 8) = *(uint4*)ll;
    } else if (b < XB + WB) {
        int g = (b - XB) * 256 + threadIdx.x;
        int row = g / GPR, part = g - row * GPR;
        __align__(16) __half hh[8];
        if (part < 98) {
            const float4* p = (const float4*)(w1 + (size_t)row * D_IN + part * 8);
            float4 a = p[0], bb = p[1];
            float v[8] = {a.x, a.y, a.z, a.w, bb.x, bb.y, bb.z, bb.w};
#pragma unroll
            for (int i = 0; i < 8; i++) hh[i] = __float2half_rn(ternf(v[i]));
        } else {
#pragma unroll
            for (int i = 0; i < 8; i++) hh[i] = __ushort_as_half(0);
        }
        *(uint4*)(g_w1h + (size_t)g * 8) = *(uint4*)hh;
    } else {
        // pack w2: 10*1024 words, 256 threads -> 40 iters
        for (int i = threadIdx.x; i < D_OUT * (D_H / 4); i += 256) {
            const float4 v = *(const float4*)(w2 + (size_t)i * 4);
            uint32_t p = (uint32_t)(terni(v.x) & 0xff)
                       | ((uint32_t)(terni(v.y) & 0xff) << 8)
                       | ((uint32_t)(terni(v.z) & 0xff) << 16)
                       | ((uint32_t)(terni(v.w) & 0xff) << 24);
            g_w2q[i] = (int)p;
        }
    }
}

// ---------------- gemm1: legacy HMMA (mma.sync) M128 x N128, hi/lo fp16 split ----------------
// Per-stage smem: A_hi 8KB | A_lo 8KB | B 8KB = 24KB; 4 stages = 96KB; bias 512B.
#define STAGE    24576
#define OFF_ALO  8192
#define OFF_B    16384
#define OFF_BIAS (STAGE * NST)          // 98304
#define SMEM_REQ (OFF_BIAS + 512)

__global__ void __launch_bounds__(256, 2) gemm1_mma_kernel(const float* __restrict__ b1) {
    extern __shared__ char smem_raw[];
    const uint32_t sb = smem_to_u32(smem_raw);
    float* s_bias = (float*)(smem_raw + OFF_BIAS);

    const int tid    = threadIdx.x;
    const int lane   = tid & 31;
    const int wid    = tid >> 5;
    const int warp_m = wid & 3;          // 4 warps over M (32 rows each)
    const int warp_n = wid >> 2;         // 2 warps over N (64 cols each)
    const int bm = blockIdx.y * 128;
    const int bn = blockIdx.x * 128;

    if (tid < 128) s_bias[tid] = b1[bn + tid];

    // ---- per-thread cp.async source/dest precompute (2 x 16B per array per stage) ----
    size_t   a_goff[2], b_goff[2];
    uint32_t sw_off[2];
#pragma unroll
    for (int j = 0; j < 2; j++) {
        int idx = tid + j * 256;          // 0..511
        int row = idx >> 2;               // 0..127
        int ch  = idx & 3;                // 16B chunk within 64B row
        sw_off[j] = (uint32_t)(row * 64 + ((ch ^ ((row >> 1) & 3)) << 4));
        a_goff[j] = (size_t)(bm + row) * KPAD + ch * 8;
        b_goff[j] = (size_t)(bn + row) * KPAD + ch * 8;
    }

    // ---- ldmatrix address precompute ----
    const int a_row = warp_m * 32 + (lane & 15);
    const int a_sel = (a_row >> 1) & 3;
    uint32_t a_base[2];
#pragma unroll
    for (int kk = 0; kk < 2; kk++)
        a_base[kk] = (uint32_t)(a_row * 64 + (((kk * 2 + (lane >> 4)) ^ a_sel) << 4));
    const int n_off = ((lane >> 4) & 1) * 8 + (lane & 7);
    const int cpar  = (lane >> 3) & 1;
    const int b_row = warp_n * 64 + n_off;
    const int b_sel = (b_row >> 1) & 3;
    uint32_t b_base[2];
#pragma unroll
    for (int kk = 0; kk < 2; kk++)
        b_base[kk] = (uint32_t)(b_row * 64 + (((kk * 2 + cpar) ^ b_sel) << 4));

    float acc[2][8][4];
#pragma unroll
    for (int mt = 0; mt < 2; mt++)
#pragma unroll
        for (int nt = 0; nt < 8; nt++)
#pragma unroll
            for (int r = 0; r < 4; r++) acc[mt][nt][r] = 0.0f;

    // ---- prologue ----
#pragma unroll
    for (int s = 0; s < NST - 1; s++) {
        const uint32_t st = sb + s * STAGE;
        const int k0 = s * 32;
#pragma unroll
        for (int j = 0; j < 2; j++) {
            cp16(st + sw_off[j],           g_xhi + a_goff[j] + k0);
            cp16(st + OFF_ALO + sw_off[j], g_xlo + a_goff[j] + k0);
            cp16(st + OFF_B + sw_off[j],   g_w1h + b_goff[j] + k0);
        }
        asm volatile("cp.async.commit_group;");
    }

    // ---- mainloop ----
    int fetch = NST - 1;
#pragma unroll 1
    for (int c = 0; c < KITER; c++) {
        asm volatile("cp.async.wait_group 2;");
        __syncthreads();

        if (fetch < KITER) {
            const uint32_t st = sb + (fetch & 3) * STAGE;
            const int k0 = fetch * 32;
#pragma unroll
            for (int j = 0; j < 2; j++) {
                cp16(st + sw_off[j],           g_xhi + a_goff[j] + k0);
                cp16(st + OFF_ALO + sw_off[j], g_xlo + a_goff[j] + k0);
                cp16(st + OFF_B + sw_off[j],   g_w1h + b_goff[j] + k0);
            }
        }
        asm volatile("cp.async.commit_group;");
        fetch++;

        const uint32_t st = sb + (c & 3) * STAGE;
#pragma unroll
        for (int kk = 0; kk < 2; kk++) {
            uint32_t ah[2][4], al[2][4], bfr[4][4];
#pragma unroll
            for (int mt = 0; mt < 2; mt++) {
                ldsm_x4(ah[mt], st + a_base[kk] + mt * 1024);
                ldsm_x4(al[mt], st + OFF_ALO + a_base[kk] + mt * 1024);
            }
#pragma unroll
            for (int nt2 = 0; nt2 < 4; nt2++)
                ldsm_x4(bfr[nt2], st + OFF_B + b_base[kk] + nt2 * 1024);
#pragma unroll
            for (int mt = 0; mt < 2; mt++)
#pragma unroll
                for (int nt = 0; nt < 8; nt++) {
                    const uint32_t* bp2 = &bfr[nt >> 1][(nt & 1) * 2];
                    mma16816(acc[mt][nt], ah[mt], bp2);
                    mma16816(acc[mt][nt], al[mt], bp2);
                }
        }
    }

    // ---- epilogue: bias + relu + store + max ----
    __shared__ float wmax[8];
    const int qrow  = lane >> 2;
    const int qcol2 = (lane & 3) * 2;
    float lmax = 0.0f;
#pragma unroll
    for (int mt = 0; mt < 2; mt++) {
#pragma unroll
        for (int nt = 0; nt < 8; nt++) {
            const int nl = warp_n * 64 + nt * 8 + qcol2;
            const int m0 = bm + warp_m * 32 + mt * 16 + qrow;
            const float bb0 = s_bias[nl], bb1 = s_bias[nl + 1];
            float v0 = fmaxf(acc[mt][nt][0] + bb0, 0.0f);
            float v1 = fmaxf(acc[mt][nt][1] + bb1, 0.0f);
            float v2 = fmaxf(acc[mt][nt][2] + bb0, 0.0f);
            float v3 = fmaxf(acc[mt][nt][3] + bb1, 0.0f);
            lmax = fmaxf(fmaxf(lmax, fmaxf(v0, v1)), fmaxf(v2, v3));
            float2 p0 = make_float2(v0, v1);
            float2 p1 = make_float2(v2, v3);
            *(float2*)(g_h + (size_t)m0 * D_H + bn + nl)       = p0;
            *(float2*)(g_h + (size_t)(m0 + 8) * D_H + bn + nl) = p1;
        }
    }
#pragma unroll
    for (int off = 16; off > 0; off >>= 1)
        lmax = fmaxf(lmax, __shfl_xor_sync(0xffffffffu, lmax, off));
    if (lane == 0) wmax[wid] = lmax;
    __syncthreads();
    if (tid == 0) {
        float m = wmax[0];
#pragma unroll
        for (int i = 1; i < 8; i++) m = fmaxf(m, wmax[i]);
        atomicMax(&g_maxbits, __float_as_uint(m));
    }
}

// ---------------- kernel 2: quant(int8) + dp4a layer2 + log_softmax ----------------
__global__ __launch_bounds__(256) void layer2_kernel(
    const float* __restrict__ b2,
    float* __restrict__ out)
{
    __shared__ int ws[D_OUT * (D_H / 4)];  // 40 KB packed int8 ternary w2

    const int tid = threadIdx.x;
#pragma unroll
    for (int i = 0; i < (D_OUT * (D_H / 4)) / 256; i++)
        ws[tid + i * 256] = g_w2q[tid + i * 256];
    __syncthreads();

    const float maxv  = __uint_as_float(g_maxbits);
    const float scale = 127.0f / maxv;

    const int lane = tid & 31, warp = tid >> 5;
    const int row  = blockIdx.x * 8 + warp;

    const float4* hrow = (const float4*)(g_h + (size_t)row * D_H);

    int acc[D_OUT];
#pragma unroll
    for (int c = 0; c < D_OUT; c++) acc[c] = 0;

#pragma unroll 4
    for (int it = lane; it < D_H / 4; it += 32) {
        float4 h4 = hrow[it];
        int q0 = __float2int_rn(fminf(h4.x * scale, 127.0f));
        int q1 = __float2int_rn(fminf(h4.y * scale, 127.0f));
        int q2 = __float2int_rn(fminf(h4.z * scale, 127.0f));
        int q3 = __float2int_rn(fminf(h4.w * scale, 127.0f));
        int pk = (int)((uint32_t)q0 | ((uint32_t)q1 << 8) | ((uint32_t)q2 << 16) | ((uint32_t)q3 << 24));
#pragma unroll
        for (int c = 0; c < D_OUT; c++)
            acc[c] = dp4a_s(pk, ws[c * (D_H / 4) + it], acc[c]);
    }

#pragma unroll
    for (int off = 16; off > 0; off >>= 1)
#pragma unroll
        for (int c = 0; c < D_OUT; c++)
            acc[c] += __shfl_xor_sync(0xffffffffu, acc[c], off);

    if (lane == 0) {
        float l[D_OUT];
        float m = -1e30f;
#pragma unroll
        for (int c = 0; c < D_OUT; c++) {
            l[c] = (float)acc[c] / scale + b2[c];
            m = fmaxf(m, l[c]);
        }
        float s = 0.0f;
#pragma unroll
        for (int c = 0; c < D_OUT; c++) s += expf(l[c] - m);
        float lse = m + logf(s);
        float* orow = out + (size_t)row * D_OUT;
#pragma unroll
        for (int c = 0; c < D_OUT; c++) orow[c] = l[c] - lse;
    }
}

// ---------------- launch ----------------
extern "C" void kernel_launch(void* const* d_in, const int* in_sizes, int n_in,
                              void* d_out, int out_size)
{
    const float* x  = (const float*)d_in[0];
    const float* w1 = (const float*)d_in[1];
    const float* b1 = (const float*)d_in[2];
    const float* w2 = (const float*)d_in[3];
    const float* b2 = (const float*)d_in[4];
    float* out = (float*)d_out;

    cudaFuncSetAttribute(gemm1_mma_kernel, cudaFuncAttributeMaxDynamicSharedMemorySize, SMEM_REQ);

    prep_kernel<<<XB + WB + 1, 256>>>(x, w1, w2);   // x split + w1 ternarize + w2 pack + max reset

    dim3 g1(D_H / 128, B_ROWS / 128);  // (32, 64)
    gemm1_mma_kernel<<<g1, 256, SMEM_REQ>>>(b1);

    layer2_kernel<<<B_ROWS / 8, 256>>>(b2, out);
}